// round 7
// baseline (speedup 1.0000x reference)
#include <cuda_runtime.h>
#include <cuda_fp16.h>
#include <cstdint>

#define BHN 16
#define SEQ 4096
#define HD 64
#define BM 128
#define BN 64
#define NTHREADS 256
#define KPITCH 72   // smem row pitch in halves (144B rows -> conflict-free LDSM)
#define NT (SEQ / BN)

// fp16 scratch copies of K and V (converted once per launch)
__device__ __half2 Ksc[BHN * SEQ * HD / 2];
__device__ __half2 Vsc[BHN * SEQ * HD / 2];

__device__ __forceinline__ float ex2f(float x) {
    float y;
    asm("ex2.approx.f32 %0, %1;" : "=f"(y) : "f"(x));
    return y;
}

__device__ __forceinline__ uint32_t packh2(float a, float b) {
    __half2 t = __floats2half2_rn(a, b);
    return reinterpret_cast<uint32_t&>(t);
}

__device__ __forceinline__ void mma16816(float c[4], const uint32_t a[4],
                                         uint32_t b0, uint32_t b1) {
    asm volatile(
        "mma.sync.aligned.m16n8k16.row.col.f32.f16.f16.f32 "
        "{%0,%1,%2,%3},{%4,%5,%6,%7},{%8,%9},{%0,%1,%2,%3};"
        : "+f"(c[0]), "+f"(c[1]), "+f"(c[2]), "+f"(c[3])
        : "r"(a[0]), "r"(a[1]), "r"(a[2]), "r"(a[3]), "r"(b0), "r"(b1));
}

__device__ __forceinline__ void ldsm_x4(uint32_t& r0, uint32_t& r1, uint32_t& r2,
                                        uint32_t& r3, uint32_t addr) {
    asm volatile("ldmatrix.sync.aligned.m8n8.x4.shared.b16 {%0,%1,%2,%3},[%4];"
                 : "=r"(r0), "=r"(r1), "=r"(r2), "=r"(r3) : "r"(addr));
}

__device__ __forceinline__ void ldsm_x4_t(uint32_t& r0, uint32_t& r1, uint32_t& r2,
                                          uint32_t& r3, uint32_t addr) {
    asm volatile("ldmatrix.sync.aligned.m8n8.x4.trans.shared.b16 {%0,%1,%2,%3},[%4];"
                 : "=r"(r0), "=r"(r1), "=r"(r2), "=r"(r3) : "r"(addr));
}

__device__ __forceinline__ void cpasync16(uint32_t dst, const void* src) {
    asm volatile("cp.async.cg.shared.global [%0],[%1],16;" :: "r"(dst), "l"(src));
}
__device__ __forceinline__ void cp_commit() {
    asm volatile("cp.async.commit_group;");
}
template <int N>
__device__ __forceinline__ void cp_wait() {
    asm volatile("cp.async.wait_group %0;" :: "n"(N));
}

// prefetch one [BN x HD] fp16 tile into padded smem, rows PERMUTED within each
// 16-key group: storage row s holds actual key a = ((s&6)<<1)|((s&8)>>2)|(s&1).
// This makes each MMA thread's owned S-columns actual-contiguous (float4 stores).
__device__ __forceinline__ void prefetch_tile(uint32_t dstbase, const __half* src,
                                              int tid) {
#pragma unroll
    for (int t = 0; t < 2; ++t) {
        int i = tid + t * NTHREADS;
        int r = i >> 3;
        int c8 = (i & 7) << 3;
        int s = r & 15;
        int a = ((s & 6) << 1) | ((s & 8) >> 2) | (s & 1);
        int srcr = (r & 48) | a;
        cpasync16(dstbase + (uint32_t)((r * KPITCH + c8) * 2), src + srcr * HD + c8);
    }
}

// ---------------- pre-conversion kernel ----------------
__global__ void __launch_bounds__(256)
convert_kernel(const float* __restrict__ K, const float* __restrict__ V) {
    const int n4 = BHN * SEQ * HD / 4;
    int i = blockIdx.x * blockDim.x + threadIdx.x;
    if (i < n4) {
        float4 f = reinterpret_cast<const float4*>(K)[i];
        Ksc[2 * i] = __floats2half2_rn(f.x, f.y);
        Ksc[2 * i + 1] = __floats2half2_rn(f.z, f.w);
    } else {
        int j = i - n4;
        float4 f = reinterpret_cast<const float4*>(V)[j];
        Vsc[2 * j] = __floats2half2_rn(f.x, f.y);
        Vsc[2 * j + 1] = __floats2half2_rn(f.z, f.w);
    }
}

// ---------------- main attention kernel ----------------
__global__ void __launch_bounds__(NTHREADS, 2)
attn_kernel(const float* __restrict__ Qg, float* __restrict__ out) {
    __shared__ __half Kb[3][BN * KPITCH];   // 3-stage, prefetch distance 2
    __shared__ __half Vb[2][BN * KPITCH];   // 2-stage, prefetch distance 1

    const int bh = blockIdx.y;
    const float* Qb = Qg + (size_t)bh * SEQ * HD;
    const __half* Kb16 = reinterpret_cast<const __half*>(Ksc) + (size_t)bh * SEQ * HD;
    const __half* Vb16 = reinterpret_cast<const __half*>(Vsc) + (size_t)bh * SEQ * HD;
    float* Ob = out + (size_t)bh * SEQ * HD;
    float* Ab = out + (size_t)BHN * SEQ * HD + (size_t)bh * SEQ * SEQ;

    const int tid = threadIdx.x;
    const int warp = tid >> 5;
    const int lane = tid & 31;
    const int g = lane >> 2;
    const int qq = lane & 3;
    const int row0 = blockIdx.x * BM + warp * 16;   // 16 rows per warp, 8 warps

    uint32_t bK[3], bV[2];
#pragma unroll
    for (int i = 0; i < 3; ++i)
        bK[i] = (uint32_t)__cvta_generic_to_shared(&Kb[i][0]);
#pragma unroll
    for (int i = 0; i < 2; ++i)
        bV[i] = (uint32_t)__cvta_generic_to_shared(&Vb[i][0]);

    // LDSM lane offsets
    const int qk_r = (lane & 7) + ((lane & 16) ? 8 : 0);
    const int qk_c = (lane & 8) ? 8 : 0;
    const uint32_t offK = (uint32_t)((qk_r * KPITCH + qk_c) * 2);
    const int v_r = (lane & 7) + ((lane & 8) ? 8 : 0);
    const int v_c = (lane & 16) ? 8 : 0;
    const uint32_t offV = (uint32_t)((v_r * KPITCH + v_c) * 2);
    const uint32_t NPOFF = 16 * KPITCH * 2;

    // ---- Q fragments fp16 (persist in regs) ----
    uint32_t qh[4][4];
#pragma unroll
    for (int kc = 0; kc < 4; ++kc)
#pragma unroll
        for (int p = 0; p < 4; ++p) {
            int r = row0 + g + (p & 1) * 8;
            int d = kc * 16 + (p >> 1) * 8 + qq * 2;
            float2 f = *reinterpret_cast<const float2*>(Qb + (size_t)r * HD + d);
            qh[kc][p] = packh2(f.x, f.y);
        }

    const float SC = 0.1803368801111244f;  // (1/sqrt(64)) * log2(e)

    // ================= PASS A: row sums =================
    float rs0 = 0.f, rs1 = 0.f;
    prefetch_tile(bK[0], Kb16, tid);
    cp_commit();
    prefetch_tile(bK[1], Kb16 + (size_t)BN * HD, tid);
    cp_commit();
    for (int kt = 0; kt < NT; ++kt) {
        if (kt + 1 < NT) cp_wait<1>(); else cp_wait<0>();
        __syncthreads();
        if (kt + 2 < NT) {
            prefetch_tile(bK[(kt + 2) % 3], Kb16 + (size_t)(kt + 2) * BN * HD, tid);
            cp_commit();
        }
        const uint32_t aK = bK[kt % 3] + offK;
        float c[8][4] = {};
#pragma unroll
        for (int kc = 0; kc < 4; ++kc) {
#pragma unroll
            for (int np = 0; np < 4; ++np) {
                uint32_t h0, h1, h2, h3;
                ldsm_x4(h0, h1, h2, h3, aK + np * NPOFF + kc * 32);
                mma16816(c[2 * np], qh[kc], h0, h1);
                mma16816(c[2 * np + 1], qh[kc], h2, h3);
            }
        }
#pragma unroll
        for (int nt = 0; nt < 8; ++nt) {
            rs0 += ex2f(c[nt][0] * SC) + ex2f(c[nt][1] * SC);
            rs1 += ex2f(c[nt][2] * SC) + ex2f(c[nt][3] * SC);
        }
    }
    rs0 += __shfl_xor_sync(0xffffffffu, rs0, 1);
    rs0 += __shfl_xor_sync(0xffffffffu, rs0, 2);
    rs1 += __shfl_xor_sync(0xffffffffu, rs1, 1);
    rs1 += __shfl_xor_sync(0xffffffffu, rs1, 2);
    const float inv0 = 1.f / rs0;
    const float inv1 = 1.f / rs1;

    // ========== PASS B: S, write attention, accumulate O ==========
    float o[8][4] = {};
    __syncthreads();   // pass-A tail: all warps done with K buffers
    prefetch_tile(bV[0], Vb16, tid);
    prefetch_tile(bK[0], Kb16, tid);
    cp_commit();
    prefetch_tile(bK[1], Kb16 + (size_t)BN * HD, tid);
    cp_commit();
    for (int kt = 0; kt < NT; ++kt) {
        if (kt + 1 < NT) cp_wait<1>(); else cp_wait<0>();
        __syncthreads();
        if (kt + 1 < NT) {
            prefetch_tile(bV[(kt + 1) & 1], Vb16 + (size_t)(kt + 1) * BN * HD, tid);
            cp_commit();
        }
        if (kt + 2 < NT) {
            prefetch_tile(bK[(kt + 2) % 3], Kb16 + (size_t)(kt + 2) * BN * HD, tid);
            cp_commit();
        }
        const uint32_t aK = bK[kt % 3] + offK;
        const uint32_t aV = bV[kt & 1] + offV;

        float c[8][4] = {};
#pragma unroll
        for (int kc = 0; kc < 4; ++kc) {
#pragma unroll
            for (int np = 0; np < 4; ++np) {
                uint32_t h0, h1, h2, h3;
                ldsm_x4(h0, h1, h2, h3, aK + np * NPOFF + kc * 32);
                mma16816(c[2 * np], qh[kc], h0, h1);
                mma16816(c[2 * np + 1], qh[kc], h2, h3);
            }
        }

        // exp + normalize + store attention as contiguous float4 (keys permuted)
        {
            float* arow0 = Ab + (size_t)(row0 + g) * SEQ + kt * BN + qq * 4;
            float* arow1 = arow0 + 8 * SEQ;
#pragma unroll
            for (int P = 0; P < 4; ++P) {
                float* p0 = c[2 * P];
                float* p1 = c[2 * P + 1];
                p0[0] = ex2f(p0[0] * SC) * inv0;
                p0[1] = ex2f(p0[1] * SC) * inv0;
                p0[2] = ex2f(p0[2] * SC) * inv1;
                p0[3] = ex2f(p0[3] * SC) * inv1;
                p1[0] = ex2f(p1[0] * SC) * inv0;
                p1[1] = ex2f(p1[1] * SC) * inv0;
                p1[2] = ex2f(p1[2] * SC) * inv1;
                p1[3] = ex2f(p1[3] * SC) * inv1;
                // thread's actual columns: kt*64 + 16P + 4qq .. +3
                __stcs(reinterpret_cast<float4*>(arow0 + 16 * P),
                       make_float4(p0[0], p0[1], p1[0], p1[1]));
                __stcs(reinterpret_cast<float4*>(arow1 + 16 * P),
                       make_float4(p0[2], p0[3], p1[2], p1[3]));
            }
        }

        // AV: P (fp16, storage order) x V (fp16, rows in same storage order)
#pragma unroll
        for (int kcp = 0; kcp < 4; ++kcp) {
            const int t0 = 2 * kcp, t1 = 2 * kcp + 1;
            uint32_t ah[4];
            ah[0] = packh2(c[t0][0], c[t0][1]);
            ah[1] = packh2(c[t0][2], c[t0][3]);
            ah[2] = packh2(c[t1][0], c[t1][1]);
            ah[3] = packh2(c[t1][2], c[t1][3]);
#pragma unroll
            for (int np = 0; np < 4; ++np) {
                uint32_t v0, v1, v2, v3;
                ldsm_x4_t(v0, v1, v2, v3, aV + kcp * NPOFF + np * 32);
                mma16816(o[2 * np], ah, v0, v1);
                mma16816(o[2 * np + 1], ah, v2, v3);
            }
        }
    }

    // ---- write O ----
#pragma unroll
    for (int nt = 0; nt < 8; ++nt) {
        int col = nt * 8 + qq * 2;
        int r = row0 + g;
        *reinterpret_cast<float2*>(Ob + (size_t)r * HD + col) =
            make_float2(o[nt][0], o[nt][1]);
        *reinterpret_cast<float2*>(Ob + (size_t)(r + 8) * HD + col) =
            make_float2(o[nt][2], o[nt][3]);
    }
}

extern "C" void kernel_launch(void* const* d_in, const int* in_sizes, int n_in,
                              void* d_out, int out_size) {
    const float* q = (const float*)d_in[0];
    const float* k = (const float*)d_in[1];
    const float* v = (const float*)d_in[2];
    (void)in_sizes; (void)n_in; (void)out_size;
    const int n4 = BHN * SEQ * HD / 4;
    convert_kernel<<<(2 * n4) / 256, 256>>>(k, v);
    dim3 grid(SEQ / BM, BHN);
    attn_kernel<<<grid, NTHREADS>>>(q, (float*)d_out);
}

// round 8
// speedup vs baseline: 1.0330x; 1.0330x over previous
#include <cuda_runtime.h>
#include <cuda_fp16.h>
#include <cstdint>

#define BHN 16
#define SEQ 4096
#define HD 64
#define BM 64
#define BN 64
#define NTHREADS 64
#define KPITCH 72   // smem row pitch in halves (144B rows -> conflict-free LDSM)
#define NT (SEQ / BN)

// fp16 scratch copies of K and V (converted once per launch)
__device__ __half2 Ksc[BHN * SEQ * HD / 2];
__device__ __half2 Vsc[BHN * SEQ * HD / 2];

__device__ __forceinline__ float ex2f(float x) {
    float y;
    asm("ex2.approx.f32 %0, %1;" : "=f"(y) : "f"(x));
    return y;
}

__device__ __forceinline__ uint32_t packh2(float a, float b) {
    __half2 t = __floats2half2_rn(a, b);
    return reinterpret_cast<uint32_t&>(t);
}

__device__ __forceinline__ void mma16816(float c[4], const uint32_t a[4],
                                         uint32_t b0, uint32_t b1) {
    asm volatile(
        "mma.sync.aligned.m16n8k16.row.col.f32.f16.f16.f32 "
        "{%0,%1,%2,%3},{%4,%5,%6,%7},{%8,%9},{%0,%1,%2,%3};"
        : "+f"(c[0]), "+f"(c[1]), "+f"(c[2]), "+f"(c[3])
        : "r"(a[0]), "r"(a[1]), "r"(a[2]), "r"(a[3]), "r"(b0), "r"(b1));
}

__device__ __forceinline__ void ldsm_x4(uint32_t& r0, uint32_t& r1, uint32_t& r2,
                                        uint32_t& r3, uint32_t addr) {
    asm volatile("ldmatrix.sync.aligned.m8n8.x4.shared.b16 {%0,%1,%2,%3},[%4];"
                 : "=r"(r0), "=r"(r1), "=r"(r2), "=r"(r3) : "r"(addr));
}

__device__ __forceinline__ void ldsm_x4_t(uint32_t& r0, uint32_t& r1, uint32_t& r2,
                                          uint32_t& r3, uint32_t addr) {
    asm volatile("ldmatrix.sync.aligned.m8n8.x4.trans.shared.b16 {%0,%1,%2,%3},[%4];"
                 : "=r"(r0), "=r"(r1), "=r"(r2), "=r"(r3) : "r"(addr));
}

__device__ __forceinline__ void cpasync16(uint32_t dst, const void* src) {
    asm volatile("cp.async.cg.shared.global [%0],[%1],16;" :: "r"(dst), "l"(src));
}
__device__ __forceinline__ void cp_commit() {
    asm volatile("cp.async.commit_group;");
}
template <int N>
__device__ __forceinline__ void cp_wait() {
    asm volatile("cp.async.wait_group %0;" :: "n"(N));
}

// prefetch one [BN x HD] fp16 tile into padded smem, rows PERMUTED within each
// 16-key group: storage row s holds actual key a = ((s&6)<<1)|((s&8)>>2)|(s&1).
// This makes each MMA thread's owned S-columns actual-contiguous (float4 stores).
__device__ __forceinline__ void prefetch_tile(uint32_t dstbase, const __half* src,
                                              int tid) {
#pragma unroll
    for (int t = 0; t < 8; ++t) {
        int i = tid + t * NTHREADS;
        int r = i >> 3;
        int c8 = (i & 7) << 3;
        int s = r & 15;
        int a = ((s & 6) << 1) | ((s & 8) >> 2) | (s & 1);
        int srcr = (r & 48) | a;
        cpasync16(dstbase + (uint32_t)((r * KPITCH + c8) * 2), src + srcr * HD + c8);
    }
}

// ---------------- pre-conversion kernel ----------------
__global__ void __launch_bounds__(256)
convert_kernel(const float* __restrict__ K, const float* __restrict__ V) {
    const int n4 = BHN * SEQ * HD / 4;
    int i = blockIdx.x * blockDim.x + threadIdx.x;
    if (i < n4) {
        float4 f = reinterpret_cast<const float4*>(K)[i];
        Ksc[2 * i] = __floats2half2_rn(f.x, f.y);
        Ksc[2 * i + 1] = __floats2half2_rn(f.z, f.w);
    } else {
        int j = i - n4;
        float4 f = reinterpret_cast<const float4*>(V)[j];
        Vsc[2 * j] = __floats2half2_rn(f.x, f.y);
        Vsc[2 * j + 1] = __floats2half2_rn(f.z, f.w);
    }
}

// ---------------- main attention kernel ----------------
// 64-thread CTAs (2 warps), 4 CTAs/SM: independent barrier domains drift out
// of phase so tensor / MUFU / LSU phases of different CTAs overlap on the SM.
__global__ void __launch_bounds__(NTHREADS, 4)
attn_kernel(const float* __restrict__ Qg, float* __restrict__ out) {
    __shared__ __half Kb[2][BN * KPITCH];
    __shared__ __half Vb[2][BN * KPITCH];

    const int bh = blockIdx.y;
    const float* Qb = Qg + (size_t)bh * SEQ * HD;
    const __half* Kb16 = reinterpret_cast<const __half*>(Ksc) + (size_t)bh * SEQ * HD;
    const __half* Vb16 = reinterpret_cast<const __half*>(Vsc) + (size_t)bh * SEQ * HD;
    float* Ob = out + (size_t)bh * SEQ * HD;
    float* Ab = out + (size_t)BHN * SEQ * HD + (size_t)bh * SEQ * SEQ;

    const int tid = threadIdx.x;
    const int warp = tid >> 5;
    const int lane = tid & 31;
    const int g = lane >> 2;
    const int qq = lane & 3;
    const int row0 = blockIdx.x * BM + warp * 32;   // 32 rows per warp, 2 warps

    const uint32_t bK0 = (uint32_t)__cvta_generic_to_shared(&Kb[0][0]);
    const uint32_t bK1 = (uint32_t)__cvta_generic_to_shared(&Kb[1][0]);
    const uint32_t bV0 = (uint32_t)__cvta_generic_to_shared(&Vb[0][0]);
    const uint32_t bV1 = (uint32_t)__cvta_generic_to_shared(&Vb[1][0]);

    // LDSM lane offsets
    const int qk_r = (lane & 7) + ((lane & 16) ? 8 : 0);
    const int qk_c = (lane & 8) ? 8 : 0;
    const uint32_t offK = (uint32_t)((qk_r * KPITCH + qk_c) * 2);
    const int v_r = (lane & 7) + ((lane & 8) ? 8 : 0);
    const int v_c = (lane & 16) ? 8 : 0;
    const uint32_t offV = (uint32_t)((v_r * KPITCH + v_c) * 2);
    const uint32_t NPOFF = 16 * KPITCH * 2;

    // ---- Q fragments fp16, two 16-row fragments per warp ----
    uint32_t qh[2][4][4];
#pragma unroll
    for (int rf = 0; rf < 2; ++rf)
#pragma unroll
        for (int kc = 0; kc < 4; ++kc)
#pragma unroll
            for (int p = 0; p < 4; ++p) {
                int r = row0 + rf * 16 + g + (p & 1) * 8;
                int d = kc * 16 + (p >> 1) * 8 + qq * 2;
                float2 f = *reinterpret_cast<const float2*>(Qb + (size_t)r * HD + d);
                qh[rf][kc][p] = packh2(f.x, f.y);
            }

    const float SC = 0.1803368801111244f;  // (1/sqrt(64)) * log2(e)

    // ================= PASS A: row sums =================
    float rs[2][2] = {};
    prefetch_tile(bK0, Kb16, tid);
    cp_commit();
    for (int kt = 0; kt < NT; ++kt) {
        if (kt + 1 < NT) {
            prefetch_tile((kt & 1) ? bK0 : bK1, Kb16 + (size_t)(kt + 1) * BN * HD, tid);
            cp_commit();
            cp_wait<1>();
        } else {
            cp_wait<0>();
        }
        __syncthreads();
        const uint32_t aK = ((kt & 1) ? bK1 : bK0) + offK;
        float c[2][8][4] = {};
#pragma unroll
        for (int kc = 0; kc < 4; ++kc) {
#pragma unroll
            for (int np = 0; np < 4; ++np) {
                uint32_t h0, h1, h2, h3;
                ldsm_x4(h0, h1, h2, h3, aK + np * NPOFF + kc * 32);
#pragma unroll
                for (int rf = 0; rf < 2; ++rf) {
                    mma16816(c[rf][2 * np], qh[rf][kc], h0, h1);
                    mma16816(c[rf][2 * np + 1], qh[rf][kc], h2, h3);
                }
            }
        }
#pragma unroll
        for (int rf = 0; rf < 2; ++rf)
#pragma unroll
            for (int nt = 0; nt < 8; ++nt) {
                rs[rf][0] += ex2f(c[rf][nt][0] * SC) + ex2f(c[rf][nt][1] * SC);
                rs[rf][1] += ex2f(c[rf][nt][2] * SC) + ex2f(c[rf][nt][3] * SC);
            }
        __syncthreads();
    }
    float inv[2][2];
#pragma unroll
    for (int rf = 0; rf < 2; ++rf)
#pragma unroll
        for (int h = 0; h < 2; ++h) {
            float v = rs[rf][h];
            v += __shfl_xor_sync(0xffffffffu, v, 1);
            v += __shfl_xor_sync(0xffffffffu, v, 2);
            inv[rf][h] = 1.f / v;
        }

    // ========== PASS B: S, write attention, accumulate O ==========
    float o[2][8][4] = {};
    prefetch_tile(bK0, Kb16, tid);
    prefetch_tile(bV0, Vb16, tid);
    cp_commit();
    for (int kt = 0; kt < NT; ++kt) {
        if (kt + 1 < NT) {
            const uint32_t dK = (kt & 1) ? bK0 : bK1;
            const uint32_t dV = (kt & 1) ? bV0 : bV1;
            prefetch_tile(dK, Kb16 + (size_t)(kt + 1) * BN * HD, tid);
            prefetch_tile(dV, Vb16 + (size_t)(kt + 1) * BN * HD, tid);
            cp_commit();
            cp_wait<1>();
        } else {
            cp_wait<0>();
        }
        __syncthreads();
        const uint32_t aK = ((kt & 1) ? bK1 : bK0) + offK;
        const uint32_t aV = ((kt & 1) ? bV1 : bV0) + offV;

        float c[2][8][4] = {};
#pragma unroll
        for (int kc = 0; kc < 4; ++kc) {
#pragma unroll
            for (int np = 0; np < 4; ++np) {
                uint32_t h0, h1, h2, h3;
                ldsm_x4(h0, h1, h2, h3, aK + np * NPOFF + kc * 32);
#pragma unroll
                for (int rf = 0; rf < 2; ++rf) {
                    mma16816(c[rf][2 * np], qh[rf][kc], h0, h1);
                    mma16816(c[rf][2 * np + 1], qh[rf][kc], h2, h3);
                }
            }
        }

        // exp + normalize + store attention as contiguous float4 (keys permuted)
#pragma unroll
        for (int rf = 0; rf < 2; ++rf) {
            const float i0 = inv[rf][0], i1 = inv[rf][1];
            float* arow0 = Ab + (size_t)(row0 + rf * 16 + g) * SEQ + kt * BN + qq * 4;
            float* arow1 = arow0 + 8 * SEQ;
#pragma unroll
            for (int P = 0; P < 4; ++P) {
                float* p0 = c[rf][2 * P];
                float* p1 = c[rf][2 * P + 1];
                p0[0] = ex2f(p0[0] * SC) * i0;
                p0[1] = ex2f(p0[1] * SC) * i0;
                p0[2] = ex2f(p0[2] * SC) * i1;
                p0[3] = ex2f(p0[3] * SC) * i1;
                p1[0] = ex2f(p1[0] * SC) * i0;
                p1[1] = ex2f(p1[1] * SC) * i0;
                p1[2] = ex2f(p1[2] * SC) * i1;
                p1[3] = ex2f(p1[3] * SC) * i1;
                // thread's actual columns: kt*64 + 16P + 4qq .. +3
                __stcs(reinterpret_cast<float4*>(arow0 + 16 * P),
                       make_float4(p0[0], p0[1], p1[0], p1[1]));
                __stcs(reinterpret_cast<float4*>(arow1 + 16 * P),
                       make_float4(p0[2], p0[3], p1[2], p1[3]));
            }
        }

        // AV: P (fp16, storage order) x V (fp16, rows in same storage order)
#pragma unroll
        for (int kcp = 0; kcp < 4; ++kcp) {
            const int t0 = 2 * kcp, t1 = 2 * kcp + 1;
            uint32_t ah[2][4];
#pragma unroll
            for (int rf = 0; rf < 2; ++rf) {
                ah[rf][0] = packh2(c[rf][t0][0], c[rf][t0][1]);
                ah[rf][1] = packh2(c[rf][t0][2], c[rf][t0][3]);
                ah[rf][2] = packh2(c[rf][t1][0], c[rf][t1][1]);
                ah[rf][3] = packh2(c[rf][t1][2], c[rf][t1][3]);
            }
#pragma unroll
            for (int np = 0; np < 4; ++np) {
                uint32_t v0, v1, v2, v3;
                ldsm_x4_t(v0, v1, v2, v3, aV + kcp * NPOFF + np * 32);
#pragma unroll
                for (int rf = 0; rf < 2; ++rf) {
                    mma16816(o[rf][2 * np], ah[rf], v0, v1);
                    mma16816(o[rf][2 * np + 1], ah[rf], v2, v3);
                }
            }
        }
        __syncthreads();
    }

    // ---- write O ----
#pragma unroll
    for (int rf = 0; rf < 2; ++rf)
#pragma unroll
        for (int nt = 0; nt < 8; ++nt) {
            int col = nt * 8 + qq * 2;
            int r = row0 + rf * 16 + g;
            *reinterpret_cast<float2*>(Ob + (size_t)r * HD + col) =
                make_float2(o[rf][nt][0], o[rf][nt][1]);
            *reinterpret_cast<float2*>(Ob + (size_t)(r + 8) * HD + col) =
                make_float2(o[rf][nt][2], o[rf][nt][3]);
        }
}

extern "C" void kernel_launch(void* const* d_in, const int* in_sizes, int n_in,
                              void* d_out, int out_size) {
    const float* q = (const float*)d_in[0];
    const float* k = (const float*)d_in[1];
    const float* v = (const float*)d_in[2];
    (void)in_sizes; (void)n_in; (void)out_size;
    const int n4 = BHN * SEQ * HD / 4;
    convert_kernel<<<(2 * n4) / 256, 256>>>(k, v);
    dim3 grid(SEQ / BM, BHN);
    attn_kernel<<<grid, NTHREADS>>>(q, (float*)d_out);
}

// round 9
// speedup vs baseline: 1.1624x; 1.1253x over previous
#include <cuda_runtime.h>
#include <cuda_fp16.h>
#include <cstdint>

#define BHN 16
#define SEQ 4096
#define HD 64
#define BM 128
#define BN 64
#define NTHREADS 128
#define KPITCH 72   // smem row pitch in halves (144B rows -> conflict-free LDSM)
#define NT (SEQ / BN)

// fp16 scratch copies of K and V (converted once per launch)
__device__ __half2 Ksc[BHN * SEQ * HD / 2];
__device__ __half2 Vsc[BHN * SEQ * HD / 2];

__device__ __forceinline__ float ex2f(float x) {
    float y;
    asm("ex2.approx.f32 %0, %1;" : "=f"(y) : "f"(x));
    return y;
}

__device__ __forceinline__ uint32_t packh2(float a, float b) {
    __half2 t = __floats2half2_rn(a, b);
    return reinterpret_cast<uint32_t&>(t);
}

__device__ __forceinline__ void mma16816(float c[4], const uint32_t a[4],
                                         uint32_t b0, uint32_t b1) {
    asm volatile(
        "mma.sync.aligned.m16n8k16.row.col.f32.f16.f16.f32 "
        "{%0,%1,%2,%3},{%4,%5,%6,%7},{%8,%9},{%0,%1,%2,%3};"
        : "+f"(c[0]), "+f"(c[1]), "+f"(c[2]), "+f"(c[3])
        : "r"(a[0]), "r"(a[1]), "r"(a[2]), "r"(a[3]), "r"(b0), "r"(b1));
}

__device__ __forceinline__ void ldsm_x4(uint32_t& r0, uint32_t& r1, uint32_t& r2,
                                        uint32_t& r3, uint32_t addr) {
    asm volatile("ldmatrix.sync.aligned.m8n8.x4.shared.b16 {%0,%1,%2,%3},[%4];"
                 : "=r"(r0), "=r"(r1), "=r"(r2), "=r"(r3) : "r"(addr));
}

__device__ __forceinline__ void ldsm_x4_t(uint32_t& r0, uint32_t& r1, uint32_t& r2,
                                          uint32_t& r3, uint32_t addr) {
    asm volatile("ldmatrix.sync.aligned.m8n8.x4.trans.shared.b16 {%0,%1,%2,%3},[%4];"
                 : "=r"(r0), "=r"(r1), "=r"(r2), "=r"(r3) : "r"(addr));
}

__device__ __forceinline__ void cpasync16(uint32_t dst, const void* src) {
    asm volatile("cp.async.cg.shared.global [%0],[%1],16;" :: "r"(dst), "l"(src));
}
__device__ __forceinline__ void cp_commit() {
    asm volatile("cp.async.commit_group;");
}
template <int N>
__device__ __forceinline__ void cp_wait() {
    asm volatile("cp.async.wait_group %0;" :: "n"(N));
}

// prefetch one [BN x HD] fp16 tile into padded smem, rows PERMUTED within each
// 16-key group: storage row s holds actual key a = ((s&6)<<1)|((s&8)>>2)|(s&1).
// This makes each MMA thread's owned S-columns actual-contiguous (float4 stores).
__device__ __forceinline__ void prefetch_tile(uint32_t dstbase, const __half* src,
                                              int tid) {
#pragma unroll
    for (int t = 0; t < 4; ++t) {
        int i = tid + t * NTHREADS;
        int r = i >> 3;
        int c8 = (i & 7) << 3;
        int s = r & 15;
        int a = ((s & 6) << 1) | ((s & 8) >> 2) | (s & 1);
        int srcr = (r & 48) | a;
        cpasync16(dstbase + (uint32_t)((r * KPITCH + c8) * 2), src + srcr * HD + c8);
    }
}

// ---------------- pre-conversion kernel ----------------
__global__ void __launch_bounds__(256)
convert_kernel(const float* __restrict__ K, const float* __restrict__ V) {
    const int n4 = BHN * SEQ * HD / 4;
    int i = blockIdx.x * blockDim.x + threadIdx.x;
    if (i < n4) {
        float4 f = reinterpret_cast<const float4*>(K)[i];
        Ksc[2 * i] = __floats2half2_rn(f.x, f.y);
        Ksc[2 * i + 1] = __floats2half2_rn(f.z, f.w);
    } else {
        int j = i - n4;
        float4 f = reinterpret_cast<const float4*>(V)[j];
        Vsc[2 * j] = __floats2half2_rn(f.x, f.y);
        Vsc[2 * j + 1] = __floats2half2_rn(f.z, f.w);
    }
}

// ---------------- main attention kernel ----------------
// np-major tile processing: each 16-key group does QK -> exp -> store -> AV
// before the next group, shrinking live S registers (64 -> 16 fp32) so that
// 3 CTAs/SM fit (12 warps/SM), and interleaving MUFU/STG with tensor work.
__global__ void __launch_bounds__(NTHREADS, 3)
attn_kernel(const float* __restrict__ Qg, float* __restrict__ out) {
    __shared__ __half Kb[2][BN * KPITCH];
    __shared__ __half Vb[2][BN * KPITCH];

    const int bh = blockIdx.y;
    const float* Qb = Qg + (size_t)bh * SEQ * HD;
    const __half* Kb16 = reinterpret_cast<const __half*>(Ksc) + (size_t)bh * SEQ * HD;
    const __half* Vb16 = reinterpret_cast<const __half*>(Vsc) + (size_t)bh * SEQ * HD;
    float* Ob = out + (size_t)bh * SEQ * HD;
    float* Ab = out + (size_t)BHN * SEQ * HD + (size_t)bh * SEQ * SEQ;

    const int tid = threadIdx.x;
    const int warp = tid >> 5;
    const int lane = tid & 31;
    const int g = lane >> 2;
    const int qq = lane & 3;
    const int row0 = blockIdx.x * BM + warp * 32;   // 32 rows per warp, 4 warps

    const uint32_t bK0 = (uint32_t)__cvta_generic_to_shared(&Kb[0][0]);
    const uint32_t bK1 = (uint32_t)__cvta_generic_to_shared(&Kb[1][0]);
    const uint32_t bV0 = (uint32_t)__cvta_generic_to_shared(&Vb[0][0]);
    const uint32_t bV1 = (uint32_t)__cvta_generic_to_shared(&Vb[1][0]);

    // LDSM lane offsets
    const int qk_r = (lane & 7) + ((lane & 16) ? 8 : 0);
    const int qk_c = (lane & 8) ? 8 : 0;
    const uint32_t offK = (uint32_t)((qk_r * KPITCH + qk_c) * 2);
    const int v_r = (lane & 7) + ((lane & 8) ? 8 : 0);
    const int v_c = (lane & 16) ? 8 : 0;
    const uint32_t offV = (uint32_t)((v_r * KPITCH + v_c) * 2);
    const uint32_t NPOFF = 16 * KPITCH * 2;

    // ---- Q fragments fp16, two 16-row fragments per warp ----
    uint32_t qh[2][4][4];
#pragma unroll
    for (int rf = 0; rf < 2; ++rf)
#pragma unroll
        for (int kc = 0; kc < 4; ++kc)
#pragma unroll
            for (int p = 0; p < 4; ++p) {
                int r = row0 + rf * 16 + g + (p & 1) * 8;
                int d = kc * 16 + (p >> 1) * 8 + qq * 2;
                float2 f = *reinterpret_cast<const float2*>(Qb + (size_t)r * HD + d);
                qh[rf][kc][p] = packh2(f.x, f.y);
            }

    const float SC = 0.1803368801111244f;  // (1/sqrt(64)) * log2(e)

    // ================= PASS A: row sums =================
    float rs[2][2] = {};
    prefetch_tile(bK0, Kb16, tid);
    cp_commit();
    for (int kt = 0; kt < NT; ++kt) {
        if (kt + 1 < NT) {
            prefetch_tile((kt & 1) ? bK0 : bK1, Kb16 + (size_t)(kt + 1) * BN * HD, tid);
            cp_commit();
            cp_wait<1>();
        } else {
            cp_wait<0>();
        }
        __syncthreads();
        const uint32_t aK = ((kt & 1) ? bK1 : bK0) + offK;
#pragma unroll
        for (int np = 0; np < 4; ++np) {
            uint32_t h[4][4];
#pragma unroll
            for (int kc = 0; kc < 4; ++kc)
                ldsm_x4(h[kc][0], h[kc][1], h[kc][2], h[kc][3],
                        aK + np * NPOFF + kc * 32);
            float ca[2][4] = {}, cb[2][4] = {};
#pragma unroll
            for (int rf = 0; rf < 2; ++rf)
#pragma unroll
                for (int kc = 0; kc < 4; ++kc) {
                    mma16816(ca[rf], qh[rf][kc], h[kc][0], h[kc][1]);
                    mma16816(cb[rf], qh[rf][kc], h[kc][2], h[kc][3]);
                }
#pragma unroll
            for (int rf = 0; rf < 2; ++rf) {
                rs[rf][0] += ex2f(ca[rf][0] * SC) + ex2f(ca[rf][1] * SC) +
                             ex2f(cb[rf][0] * SC) + ex2f(cb[rf][1] * SC);
                rs[rf][1] += ex2f(ca[rf][2] * SC) + ex2f(ca[rf][3] * SC) +
                             ex2f(cb[rf][2] * SC) + ex2f(cb[rf][3] * SC);
            }
        }
        __syncthreads();
    }
    float inv[2][2];
#pragma unroll
    for (int rf = 0; rf < 2; ++rf)
#pragma unroll
        for (int h = 0; h < 2; ++h) {
            float v = rs[rf][h];
            v += __shfl_xor_sync(0xffffffffu, v, 1);
            v += __shfl_xor_sync(0xffffffffu, v, 2);
            inv[rf][h] = 1.f / v;
        }

    // ========== PASS B: S, write attention, accumulate O ==========
    float o[2][8][4] = {};
    prefetch_tile(bK0, Kb16, tid);
    prefetch_tile(bV0, Vb16, tid);
    cp_commit();
    for (int kt = 0; kt < NT; ++kt) {
        if (kt + 1 < NT) {
            const uint32_t dK = (kt & 1) ? bK0 : bK1;
            const uint32_t dV = (kt & 1) ? bV0 : bV1;
            prefetch_tile(dK, Kb16 + (size_t)(kt + 1) * BN * HD, tid);
            prefetch_tile(dV, Vb16 + (size_t)(kt + 1) * BN * HD, tid);
            cp_commit();
            cp_wait<1>();
        } else {
            cp_wait<0>();
        }
        __syncthreads();
        const uint32_t aK = ((kt & 1) ? bK1 : bK0) + offK;
        const uint32_t aV = ((kt & 1) ? bV1 : bV0) + offV;

        // np-major: per 16-key group, QK -> exp/normalize -> store -> pack -> AV
#pragma unroll
        for (int np = 0; np < 4; ++np) {
            uint32_t h[4][4];
#pragma unroll
            for (int kc = 0; kc < 4; ++kc)
                ldsm_x4(h[kc][0], h[kc][1], h[kc][2], h[kc][3],
                        aK + np * NPOFF + kc * 32);
            float ca[2][4] = {}, cb[2][4] = {};
#pragma unroll
            for (int rf = 0; rf < 2; ++rf)
#pragma unroll
                for (int kc = 0; kc < 4; ++kc) {
                    mma16816(ca[rf], qh[rf][kc], h[kc][0], h[kc][1]);
                    mma16816(cb[rf], qh[rf][kc], h[kc][2], h[kc][3]);
                }

            uint32_t ah[2][4];
#pragma unroll
            for (int rf = 0; rf < 2; ++rf) {
                const float i0 = inv[rf][0], i1 = inv[rf][1];
                ca[rf][0] = ex2f(ca[rf][0] * SC) * i0;
                ca[rf][1] = ex2f(ca[rf][1] * SC) * i0;
                ca[rf][2] = ex2f(ca[rf][2] * SC) * i1;
                ca[rf][3] = ex2f(ca[rf][3] * SC) * i1;
                cb[rf][0] = ex2f(cb[rf][0] * SC) * i0;
                cb[rf][1] = ex2f(cb[rf][1] * SC) * i0;
                cb[rf][2] = ex2f(cb[rf][2] * SC) * i1;
                cb[rf][3] = ex2f(cb[rf][3] * SC) * i1;
                // thread's actual columns: kt*64 + 16*np + 4qq .. +3
                float* arow0 = Ab + (size_t)(row0 + rf * 16 + g) * SEQ +
                               kt * BN + 16 * np + qq * 4;
                __stcs(reinterpret_cast<float4*>(arow0),
                       make_float4(ca[rf][0], ca[rf][1], cb[rf][0], cb[rf][1]));
                __stcs(reinterpret_cast<float4*>(arow0 + 8 * SEQ),
                       make_float4(ca[rf][2], ca[rf][3], cb[rf][2], cb[rf][3]));
                ah[rf][0] = packh2(ca[rf][0], ca[rf][1]);
                ah[rf][1] = packh2(ca[rf][2], ca[rf][3]);
                ah[rf][2] = packh2(cb[rf][0], cb[rf][1]);
                ah[rf][3] = packh2(cb[rf][2], cb[rf][3]);
            }

            // AV for this 16-key group over all 64 output columns
#pragma unroll
            for (int nd = 0; nd < 4; ++nd) {
                uint32_t v0, v1, v2, v3;
                ldsm_x4_t(v0, v1, v2, v3, aV + np * NPOFF + nd * 32);
#pragma unroll
                for (int rf = 0; rf < 2; ++rf) {
                    mma16816(o[rf][2 * nd], ah[rf], v0, v1);
                    mma16816(o[rf][2 * nd + 1], ah[rf], v2, v3);
                }
            }
        }
        __syncthreads();
    }

    // ---- write O ----
#pragma unroll
    for (int rf = 0; rf < 2; ++rf)
#pragma unroll
        for (int nt = 0; nt < 8; ++nt) {
            int col = nt * 8 + qq * 2;
            int r = row0 + rf * 16 + g;
            *reinterpret_cast<float2*>(Ob + (size_t)r * HD + col) =
                make_float2(o[rf][nt][0], o[rf][nt][1]);
            *reinterpret_cast<float2*>(Ob + (size_t)(r + 8) * HD + col) =
                make_float2(o[rf][nt][2], o[rf][nt][3]);
        }
}

extern "C" void kernel_launch(void* const* d_in, const int* in_sizes, int n_in,
                              void* d_out, int out_size) {
    const float* q = (const float*)d_in[0];
    const float* k = (const float*)d_in[1];
    const float* v = (const float*)d_in[2];
    (void)in_sizes; (void)n_in; (void)out_size;
    const int n4 = BHN * SEQ * HD / 4;
    convert_kernel<<<(2 * n4) / 256, 256>>>(k, v);
    dim3 grid(SEQ / BM, BHN);
    attn_kernel<<<grid, NTHREADS>>>(q, (float*)d_out);
}

// round 10
// speedup vs baseline: 1.2529x; 1.0779x over previous
#include <cuda_runtime.h>
#include <cuda_fp16.h>
#include <cstdint>

#define BHN 16
#define SEQ 4096
#define HD 64
#define BM 128
#define BN 64
#define NTHREADS 128
#define KPITCH 72   // smem row pitch in halves (144B rows -> conflict-free LDSM)
#define NT (SEQ / BN)

// fp16 scratch copies of K and V (converted once per launch)
__device__ __half2 Ksc[BHN * SEQ * HD / 2];
__device__ __half2 Vsc[BHN * SEQ * HD / 2];

__device__ __forceinline__ float ex2f(float x) {
    float y;
    asm("ex2.approx.f32 %0, %1;" : "=f"(y) : "f"(x));
    return y;
}

// packed fp16 exp2 of two halves
__device__ __forceinline__ uint32_t h2ex2(uint32_t x) {
    uint32_t y;
    asm("ex2.approx.f16x2 %0, %1;" : "=r"(y) : "r"(x));
    return y;
}

__device__ __forceinline__ uint32_t packh2(float a, float b) {
    __half2 t = __floats2half2_rn(a, b);
    return reinterpret_cast<uint32_t&>(t);
}

__device__ __forceinline__ uint32_t hadd2u(uint32_t a, uint32_t b) {
    __half2 r = __hadd2(reinterpret_cast<__half2&>(a), reinterpret_cast<__half2&>(b));
    return reinterpret_cast<uint32_t&>(r);
}

__device__ __forceinline__ void mma16816(float c[4], const uint32_t a[4],
                                         uint32_t b0, uint32_t b1) {
    asm volatile(
        "mma.sync.aligned.m16n8k16.row.col.f32.f16.f16.f32 "
        "{%0,%1,%2,%3},{%4,%5,%6,%7},{%8,%9},{%0,%1,%2,%3};"
        : "+f"(c[0]), "+f"(c[1]), "+f"(c[2]), "+f"(c[3])
        : "r"(a[0]), "r"(a[1]), "r"(a[2]), "r"(a[3]), "r"(b0), "r"(b1));
}

__device__ __forceinline__ void ldsm_x4(uint32_t& r0, uint32_t& r1, uint32_t& r2,
                                        uint32_t& r3, uint32_t addr) {
    asm volatile("ldmatrix.sync.aligned.m8n8.x4.shared.b16 {%0,%1,%2,%3},[%4];"
                 : "=r"(r0), "=r"(r1), "=r"(r2), "=r"(r3) : "r"(addr));
}

__device__ __forceinline__ void ldsm_x4_t(uint32_t& r0, uint32_t& r1, uint32_t& r2,
                                          uint32_t& r3, uint32_t addr) {
    asm volatile("ldmatrix.sync.aligned.m8n8.x4.trans.shared.b16 {%0,%1,%2,%3},[%4];"
                 : "=r"(r0), "=r"(r1), "=r"(r2), "=r"(r3) : "r"(addr));
}

__device__ __forceinline__ void cpasync16(uint32_t dst, const void* src) {
    asm volatile("cp.async.cg.shared.global [%0],[%1],16;" :: "r"(dst), "l"(src));
}
__device__ __forceinline__ void cp_commit() {
    asm volatile("cp.async.commit_group;");
}
template <int N>
__device__ __forceinline__ void cp_wait() {
    asm volatile("cp.async.wait_group %0;" :: "n"(N));
}

// prefetch one [BN x HD] fp16 tile into padded smem, rows PERMUTED within each
// 16-key group: storage row s holds actual key a = ((s&6)<<1)|((s&8)>>2)|(s&1).
// This makes each MMA thread's owned S-columns actual-contiguous (float4 stores).
__device__ __forceinline__ void prefetch_tile(uint32_t dstbase, const __half* src,
                                              int tid) {
#pragma unroll
    for (int t = 0; t < 4; ++t) {
        int i = tid + t * NTHREADS;
        int r = i >> 3;
        int c8 = (i & 7) << 3;
        int s = r & 15;
        int a = ((s & 6) << 1) | ((s & 8) >> 2) | (s & 1);
        int srcr = (r & 48) | a;
        cpasync16(dstbase + (uint32_t)((r * KPITCH + c8) * 2), src + srcr * HD + c8);
    }
}

// ---------------- pre-conversion kernel ----------------
__global__ void __launch_bounds__(256)
convert_kernel(const float* __restrict__ K, const float* __restrict__ V) {
    const int n4 = BHN * SEQ * HD / 4;
    int i = blockIdx.x * blockDim.x + threadIdx.x;
    if (i < n4) {
        float4 f = reinterpret_cast<const float4*>(K)[i];
        Ksc[2 * i] = __floats2half2_rn(f.x, f.y);
        Ksc[2 * i + 1] = __floats2half2_rn(f.z, f.w);
    } else {
        int j = i - n4;
        float4 f = reinterpret_cast<const float4*>(V)[j];
        Vsc[2 * j] = __floats2half2_rn(f.x, f.y);
        Vsc[2 * j + 1] = __floats2half2_rn(f.z, f.w);
    }
}

// ---------------- main attention kernel ----------------
// np-major tile processing + Q pre-scaled by SC (logits arrive ready for exp2)
// + fp16x2 exp in pass A + normalization folded into the exponent in pass B.
__global__ void __launch_bounds__(NTHREADS, 3)
attn_kernel(const float* __restrict__ Qg, float* __restrict__ out) {
    __shared__ __half Kb[2][BN * KPITCH];
    __shared__ __half Vb[2][BN * KPITCH];

    const int bh = blockIdx.y;
    const float* Qb = Qg + (size_t)bh * SEQ * HD;
    const __half* Kb16 = reinterpret_cast<const __half*>(Ksc) + (size_t)bh * SEQ * HD;
    const __half* Vb16 = reinterpret_cast<const __half*>(Vsc) + (size_t)bh * SEQ * HD;
    float* Ob = out + (size_t)bh * SEQ * HD;
    float* Ab = out + (size_t)BHN * SEQ * HD + (size_t)bh * SEQ * SEQ;

    const int tid = threadIdx.x;
    const int warp = tid >> 5;
    const int lane = tid & 31;
    const int g = lane >> 2;
    const int qq = lane & 3;
    const int row0 = blockIdx.x * BM + warp * 32;   // 32 rows per warp, 4 warps

    const uint32_t bK0 = (uint32_t)__cvta_generic_to_shared(&Kb[0][0]);
    const uint32_t bK1 = (uint32_t)__cvta_generic_to_shared(&Kb[1][0]);
    const uint32_t bV0 = (uint32_t)__cvta_generic_to_shared(&Vb[0][0]);
    const uint32_t bV1 = (uint32_t)__cvta_generic_to_shared(&Vb[1][0]);

    // LDSM lane offsets
    const int qk_r = (lane & 7) + ((lane & 16) ? 8 : 0);
    const int qk_c = (lane & 8) ? 8 : 0;
    const uint32_t offK = (uint32_t)((qk_r * KPITCH + qk_c) * 2);
    const int v_r = (lane & 7) + ((lane & 8) ? 8 : 0);
    const int v_c = (lane & 16) ? 8 : 0;
    const uint32_t offV = (uint32_t)((v_r * KPITCH + v_c) * 2);
    const uint32_t NPOFF = 16 * KPITCH * 2;

    const float SC = 0.1803368801111244f;  // (1/sqrt(64)) * log2(e)

    // ---- Q fragments fp16, PRE-SCALED by SC: MMA outputs are exp2-ready ----
    uint32_t qh[2][4][4];
#pragma unroll
    for (int rf = 0; rf < 2; ++rf)
#pragma unroll
        for (int kc = 0; kc < 4; ++kc)
#pragma unroll
            for (int p = 0; p < 4; ++p) {
                int r = row0 + rf * 16 + g + (p & 1) * 8;
                int d = kc * 16 + (p >> 1) * 8 + qq * 2;
                float2 f = *reinterpret_cast<const float2*>(Qb + (size_t)r * HD + d);
                qh[rf][kc][p] = packh2(f.x * SC, f.y * SC);
            }

    // ================= PASS A: row sums (fp16x2 exp, half2 accumulate) ========
    float rs[2][2] = {};
    prefetch_tile(bK0, Kb16, tid);
    cp_commit();
    for (int kt = 0; kt < NT; ++kt) {
        if (kt + 1 < NT) {
            prefetch_tile((kt & 1) ? bK0 : bK1, Kb16 + (size_t)(kt + 1) * BN * HD, tid);
            cp_commit();
            cp_wait<1>();
        } else {
            cp_wait<0>();
        }
        __syncthreads();
        const uint32_t aK = ((kt & 1) ? bK1 : bK0) + offK;
        uint32_t acc0[2] = {0, 0}, acc1[2] = {0, 0};   // half2 per-tile accumulators
#pragma unroll
        for (int np = 0; np < 4; ++np) {
            uint32_t h[4][4];
#pragma unroll
            for (int kc = 0; kc < 4; ++kc)
                ldsm_x4(h[kc][0], h[kc][1], h[kc][2], h[kc][3],
                        aK + np * NPOFF + kc * 32);
            float ca[2][4] = {}, cb[2][4] = {};
#pragma unroll
            for (int rf = 0; rf < 2; ++rf)
#pragma unroll
                for (int kc = 0; kc < 4; ++kc) {
                    mma16816(ca[rf], qh[rf][kc], h[kc][0], h[kc][1]);
                    mma16816(cb[rf], qh[rf][kc], h[kc][2], h[kc][3]);
                }
#pragma unroll
            for (int rf = 0; rf < 2; ++rf) {
                uint32_t e0 = h2ex2(packh2(ca[rf][0], ca[rf][1]));
                uint32_t e1 = h2ex2(packh2(cb[rf][0], cb[rf][1]));
                uint32_t e2 = h2ex2(packh2(ca[rf][2], ca[rf][3]));
                uint32_t e3 = h2ex2(packh2(cb[rf][2], cb[rf][3]));
                acc0[rf] = hadd2u(acc0[rf], hadd2u(e0, e1));
                acc1[rf] = hadd2u(acc1[rf], hadd2u(e2, e3));
            }
        }
        // flush per-tile half2 partials into fp32 row sums
#pragma unroll
        for (int rf = 0; rf < 2; ++rf) {
            float2 f0 = __half22float2(reinterpret_cast<__half2&>(acc0[rf]));
            float2 f1 = __half22float2(reinterpret_cast<__half2&>(acc1[rf]));
            rs[rf][0] += f0.x + f0.y;
            rs[rf][1] += f1.x + f1.y;
        }
        __syncthreads();
    }
    float linv[2][2];
#pragma unroll
    for (int rf = 0; rf < 2; ++rf)
#pragma unroll
        for (int h = 0; h < 2; ++h) {
            float v = rs[rf][h];
            v += __shfl_xor_sync(0xffffffffu, v, 1);
            v += __shfl_xor_sync(0xffffffffu, v, 2);
            linv[rf][h] = -__log2f(v);   // normalization folded into exponent
        }

    // ========== PASS B: S, write attention, accumulate O ==========
    float o[2][8][4] = {};
    prefetch_tile(bK0, Kb16, tid);
    prefetch_tile(bV0, Vb16, tid);
    cp_commit();
    for (int kt = 0; kt < NT; ++kt) {
        if (kt + 1 < NT) {
            const uint32_t dK = (kt & 1) ? bK0 : bK1;
            const uint32_t dV = (kt & 1) ? bV0 : bV1;
            prefetch_tile(dK, Kb16 + (size_t)(kt + 1) * BN * HD, tid);
            prefetch_tile(dV, Vb16 + (size_t)(kt + 1) * BN * HD, tid);
            cp_commit();
            cp_wait<1>();
        } else {
            cp_wait<0>();
        }
        __syncthreads();
        const uint32_t aK = ((kt & 1) ? bK1 : bK0) + offK;
        const uint32_t aV = ((kt & 1) ? bV1 : bV0) + offV;

        // np-major: per 16-key group, QK -> exp(s+linv) -> store -> pack -> AV
#pragma unroll
        for (int np = 0; np < 4; ++np) {
            uint32_t h[4][4];
#pragma unroll
            for (int kc = 0; kc < 4; ++kc)
                ldsm_x4(h[kc][0], h[kc][1], h[kc][2], h[kc][3],
                        aK + np * NPOFF + kc * 32);
            float ca[2][4] = {}, cb[2][4] = {};
#pragma unroll
            for (int rf = 0; rf < 2; ++rf)
#pragma unroll
                for (int kc = 0; kc < 4; ++kc) {
                    mma16816(ca[rf], qh[rf][kc], h[kc][0], h[kc][1]);
                    mma16816(cb[rf], qh[rf][kc], h[kc][2], h[kc][3]);
                }

            uint32_t ah[2][4];
#pragma unroll
            for (int rf = 0; rf < 2; ++rf) {
                const float l0 = linv[rf][0], l1 = linv[rf][1];
                ca[rf][0] = ex2f(ca[rf][0] + l0);
                ca[rf][1] = ex2f(ca[rf][1] + l0);
                ca[rf][2] = ex2f(ca[rf][2] + l1);
                ca[rf][3] = ex2f(ca[rf][3] + l1);
                cb[rf][0] = ex2f(cb[rf][0] + l0);
                cb[rf][1] = ex2f(cb[rf][1] + l0);
                cb[rf][2] = ex2f(cb[rf][2] + l1);
                cb[rf][3] = ex2f(cb[rf][3] + l1);
                // thread's actual columns: kt*64 + 16*np + 4qq .. +3
                float* arow0 = Ab + (size_t)(row0 + rf * 16 + g) * SEQ +
                               kt * BN + 16 * np + qq * 4;
                __stcs(reinterpret_cast<float4*>(arow0),
                       make_float4(ca[rf][0], ca[rf][1], cb[rf][0], cb[rf][1]));
                __stcs(reinterpret_cast<float4*>(arow0 + 8 * SEQ),
                       make_float4(ca[rf][2], ca[rf][3], cb[rf][2], cb[rf][3]));
                ah[rf][0] = packh2(ca[rf][0], ca[rf][1]);
                ah[rf][1] = packh2(ca[rf][2], ca[rf][3]);
                ah[rf][2] = packh2(cb[rf][0], cb[rf][1]);
                ah[rf][3] = packh2(cb[rf][2], cb[rf][3]);
            }

            // AV for this 16-key group over all 64 output columns
#pragma unroll
            for (int nd = 0; nd < 4; ++nd) {
                uint32_t v0, v1, v2, v3;
                ldsm_x4_t(v0, v1, v2, v3, aV + np * NPOFF + nd * 32);
#pragma unroll
                for (int rf = 0; rf < 2; ++rf) {
                    mma16816(o[rf][2 * nd], ah[rf], v0, v1);
                    mma16816(o[rf][2 * nd + 1], ah[rf], v2, v3);
                }
            }
        }
        __syncthreads();
    }

    // ---- write O ----
#pragma unroll
    for (int rf = 0; rf < 2; ++rf)
#pragma unroll
        for (int nt = 0; nt < 8; ++nt) {
            int col = nt * 8 + qq * 2;
            int r = row0 + rf * 16 + g;
            *reinterpret_cast<float2*>(Ob + (size_t)r * HD + col) =
                make_float2(o[rf][nt][0], o[rf][nt][1]);
            *reinterpret_cast<float2*>(Ob + (size_t)(r + 8) * HD + col) =
                make_float2(o[rf][nt][2], o[rf][nt][3]);
        }
}

extern "C" void kernel_launch(void* const* d_in, const int* in_sizes, int n_in,
                              void* d_out, int out_size) {
    const float* q = (const float*)d_in[0];
    const float* k = (const float*)d_in[1];
    const float* v = (const float*)d_in[2];
    (void)in_sizes; (void)n_in; (void)out_size;
    const int n4 = BHN * SEQ * HD / 4;
    convert_kernel<<<(2 * n4) / 256, 256>>>(k, v);
    dim3 grid(SEQ / BM, BHN);
    attn_kernel<<<grid, NTHREADS>>>(q, (float*)d_out);
}

// round 11
// speedup vs baseline: 1.3003x; 1.0378x over previous
#include <cuda_runtime.h>
#include <cuda_fp16.h>
#include <cstdint>

#define BHN 16
#define SEQ 4096
#define HD 64
#define BM 128
#define BN 64
#define NTHREADS 128
#define KPITCH 72   // smem row pitch in halves (144B rows -> conflict-free LDSM)
#define NT (SEQ / BN)

// fp16 scratch copies of K and V (converted once per launch)
__device__ __half2 Ksc[BHN * SEQ * HD / 2];
__device__ __half2 Vsc[BHN * SEQ * HD / 2];
// per-row -log2(rowsum), produced by rowsum_kernel, consumed by attn_kernel
__device__ float LinvG[BHN * SEQ];

__device__ __forceinline__ float ex2f(float x) {
    float y;
    asm("ex2.approx.f32 %0, %1;" : "=f"(y) : "f"(x));
    return y;
}

// packed fp16 exp2 of two halves
__device__ __forceinline__ uint32_t h2ex2(uint32_t x) {
    uint32_t y;
    asm("ex2.approx.f16x2 %0, %1;" : "=r"(y) : "r"(x));
    return y;
}

__device__ __forceinline__ uint32_t packh2(float a, float b) {
    __half2 t = __floats2half2_rn(a, b);
    return reinterpret_cast<uint32_t&>(t);
}

__device__ __forceinline__ uint32_t hadd2u(uint32_t a, uint32_t b) {
    __half2 r = __hadd2(reinterpret_cast<__half2&>(a), reinterpret_cast<__half2&>(b));
    return reinterpret_cast<uint32_t&>(r);
}

// fp32-accumulator fp16 MMA
__device__ __forceinline__ void mma16816(float c[4], const uint32_t a[4],
                                         uint32_t b0, uint32_t b1) {
    asm volatile(
        "mma.sync.aligned.m16n8k16.row.col.f32.f16.f16.f32 "
        "{%0,%1,%2,%3},{%4,%5,%6,%7},{%8,%9},{%0,%1,%2,%3};"
        : "+f"(c[0]), "+f"(c[1]), "+f"(c[2]), "+f"(c[3])
        : "r"(a[0]), "r"(a[1]), "r"(a[2]), "r"(a[3]), "r"(b0), "r"(b1));
}

// fp16-accumulator fp16 MMA (D/C packed half2 x2) — used for pass-A logits only
__device__ __forceinline__ void mma16816h(uint32_t c[2], const uint32_t a[4],
                                          uint32_t b0, uint32_t b1) {
    asm volatile(
        "mma.sync.aligned.m16n8k16.row.col.f16.f16.f16.f16 "
        "{%0,%1},{%2,%3,%4,%5},{%6,%7},{%0,%1};"
        : "+r"(c[0]), "+r"(c[1])
        : "r"(a[0]), "r"(a[1]), "r"(a[2]), "r"(a[3]), "r"(b0), "r"(b1));
}

__device__ __forceinline__ void ldsm_x4(uint32_t& r0, uint32_t& r1, uint32_t& r2,
                                        uint32_t& r3, uint32_t addr) {
    asm volatile("ldmatrix.sync.aligned.m8n8.x4.shared.b16 {%0,%1,%2,%3},[%4];"
                 : "=r"(r0), "=r"(r1), "=r"(r2), "=r"(r3) : "r"(addr));
}

__device__ __forceinline__ void ldsm_x4_t(uint32_t& r0, uint32_t& r1, uint32_t& r2,
                                          uint32_t& r3, uint32_t addr) {
    asm volatile("ldmatrix.sync.aligned.m8n8.x4.trans.shared.b16 {%0,%1,%2,%3},[%4];"
                 : "=r"(r0), "=r"(r1), "=r"(r2), "=r"(r3) : "r"(addr));
}

__device__ __forceinline__ void cpasync16(uint32_t dst, const void* src) {
    asm volatile("cp.async.cg.shared.global [%0],[%1],16;" :: "r"(dst), "l"(src));
}
__device__ __forceinline__ void cp_commit() {
    asm volatile("cp.async.commit_group;");
}
template <int N>
__device__ __forceinline__ void cp_wait() {
    asm volatile("cp.async.wait_group %0;" :: "n"(N));
}

// prefetch one [BN x HD] fp16 tile into padded smem, rows PERMUTED within each
// 16-key group: storage row s holds actual key a = ((s&6)<<1)|((s&8)>>2)|(s&1).
__device__ __forceinline__ void prefetch_tile(uint32_t dstbase, const __half* src,
                                              int tid) {
#pragma unroll
    for (int t = 0; t < 4; ++t) {
        int i = tid + t * NTHREADS;
        int r = i >> 3;
        int c8 = (i & 7) << 3;
        int s = r & 15;
        int a = ((s & 6) << 1) | ((s & 8) >> 2) | (s & 1);
        int srcr = (r & 48) | a;
        cpasync16(dstbase + (uint32_t)((r * KPITCH + c8) * 2), src + srcr * HD + c8);
    }
}

// ---------------- pre-conversion kernel ----------------
__global__ void __launch_bounds__(256)
convert_kernel(const float* __restrict__ K, const float* __restrict__ V) {
    const int n4 = BHN * SEQ * HD / 4;
    int i = blockIdx.x * blockDim.x + threadIdx.x;
    if (i < n4) {
        float4 f = reinterpret_cast<const float4*>(K)[i];
        Ksc[2 * i] = __floats2half2_rn(f.x, f.y);
        Ksc[2 * i + 1] = __floats2half2_rn(f.z, f.w);
    } else {
        int j = i - n4;
        float4 f = reinterpret_cast<const float4*>(V)[j];
        Vsc[2 * j] = __floats2half2_rn(f.x, f.y);
        Vsc[2 * j + 1] = __floats2half2_rn(f.z, f.w);
    }
}

// ---------------- PASS A kernel: row sums via f16-accum MMA ----------------
// Lean register footprint -> 5 CTAs/SM (20 warps) to hide MMA/LDSM latency.
__global__ void __launch_bounds__(NTHREADS, 5)
rowsum_kernel(const float* __restrict__ Qg) {
    __shared__ __half Kb[2][BN * KPITCH];

    const int bh = blockIdx.y;
    const float* Qb = Qg + (size_t)bh * SEQ * HD;
    const __half* Kb16 = reinterpret_cast<const __half*>(Ksc) + (size_t)bh * SEQ * HD;

    const int tid = threadIdx.x;
    const int warp = tid >> 5;
    const int lane = tid & 31;
    const int g = lane >> 2;
    const int qq = lane & 3;
    const int row0 = blockIdx.x * BM + warp * 32;

    const uint32_t bK0 = (uint32_t)__cvta_generic_to_shared(&Kb[0][0]);
    const uint32_t bK1 = (uint32_t)__cvta_generic_to_shared(&Kb[1][0]);

    const int qk_r = (lane & 7) + ((lane & 16) ? 8 : 0);
    const int qk_c = (lane & 8) ? 8 : 0;
    const uint32_t offK = (uint32_t)((qk_r * KPITCH + qk_c) * 2);
    const uint32_t NPOFF = 16 * KPITCH * 2;

    const float SC = 0.1803368801111244f;  // (1/sqrt(64)) * log2(e)

    // Q fragments fp16, pre-scaled by SC
    uint32_t qh[2][4][4];
#pragma unroll
    for (int rf = 0; rf < 2; ++rf)
#pragma unroll
        for (int kc = 0; kc < 4; ++kc)
#pragma unroll
            for (int p = 0; p < 4; ++p) {
                int r = row0 + rf * 16 + g + (p & 1) * 8;
                int d = kc * 16 + (p >> 1) * 8 + qq * 2;
                float2 f = *reinterpret_cast<const float2*>(Qb + (size_t)r * HD + d);
                qh[rf][kc][p] = packh2(f.x * SC, f.y * SC);
            }

    float rs[2][2] = {};
    prefetch_tile(bK0, Kb16, tid);
    cp_commit();
    for (int kt = 0; kt < NT; ++kt) {
        if (kt + 1 < NT) {
            prefetch_tile((kt & 1) ? bK0 : bK1, Kb16 + (size_t)(kt + 1) * BN * HD, tid);
            cp_commit();
            cp_wait<1>();
        } else {
            cp_wait<0>();
        }
        __syncthreads();
        const uint32_t aK = ((kt & 1) ? bK1 : bK0) + offK;
        uint32_t acc[2][2] = {{0, 0}, {0, 0}};   // [rf][row-half], half2 sums
#pragma unroll
        for (int np = 0; np < 4; ++np) {
            uint32_t h[4][4];
#pragma unroll
            for (int kc = 0; kc < 4; ++kc)
                ldsm_x4(h[kc][0], h[kc][1], h[kc][2], h[kc][3],
                        aK + np * NPOFF + kc * 32);
#pragma unroll
            for (int rf = 0; rf < 2; ++rf) {
                uint32_t ca[2] = {0, 0}, cb[2] = {0, 0};
#pragma unroll
                for (int kc = 0; kc < 4; ++kc) {
                    mma16816h(ca, qh[rf][kc], h[kc][0], h[kc][1]);
                    mma16816h(cb, qh[rf][kc], h[kc][2], h[kc][3]);
                }
                // ca[0]/cb[0]: row g cols, ca[1]/cb[1]: row g+8 cols (packed h2)
                acc[rf][0] = hadd2u(acc[rf][0], hadd2u(h2ex2(ca[0]), h2ex2(cb[0])));
                acc[rf][1] = hadd2u(acc[rf][1], hadd2u(h2ex2(ca[1]), h2ex2(cb[1])));
            }
        }
#pragma unroll
        for (int rf = 0; rf < 2; ++rf) {
            float2 f0 = __half22float2(reinterpret_cast<__half2&>(acc[rf][0]));
            float2 f1 = __half22float2(reinterpret_cast<__half2&>(acc[rf][1]));
            rs[rf][0] += f0.x + f0.y;
            rs[rf][1] += f1.x + f1.y;
        }
        __syncthreads();
    }
#pragma unroll
    for (int rf = 0; rf < 2; ++rf)
#pragma unroll
        for (int h = 0; h < 2; ++h) {
            float v = rs[rf][h];
            v += __shfl_xor_sync(0xffffffffu, v, 1);
            v += __shfl_xor_sync(0xffffffffu, v, 2);
            if (qq == 0)
                LinvG[bh * SEQ + row0 + rf * 16 + g + h * 8] = -__log2f(v);
        }
}

// ---------------- PASS B kernel: S, attention write, O accumulate ----------
__global__ void __launch_bounds__(NTHREADS, 3)
attn_kernel(const float* __restrict__ Qg, float* __restrict__ out) {
    __shared__ __half Kb[2][BN * KPITCH];
    __shared__ __half Vb[2][BN * KPITCH];

    const int bh = blockIdx.y;
    const float* Qb = Qg + (size_t)bh * SEQ * HD;
    const __half* Kb16 = reinterpret_cast<const __half*>(Ksc) + (size_t)bh * SEQ * HD;
    const __half* Vb16 = reinterpret_cast<const __half*>(Vsc) + (size_t)bh * SEQ * HD;
    float* Ob = out + (size_t)bh * SEQ * HD;
    float* Ab = out + (size_t)BHN * SEQ * HD + (size_t)bh * SEQ * SEQ;

    const int tid = threadIdx.x;
    const int warp = tid >> 5;
    const int lane = tid & 31;
    const int g = lane >> 2;
    const int qq = lane & 3;
    const int row0 = blockIdx.x * BM + warp * 32;

    const uint32_t bK0 = (uint32_t)__cvta_generic_to_shared(&Kb[0][0]);
    const uint32_t bK1 = (uint32_t)__cvta_generic_to_shared(&Kb[1][0]);
    const uint32_t bV0 = (uint32_t)__cvta_generic_to_shared(&Vb[0][0]);
    const uint32_t bV1 = (uint32_t)__cvta_generic_to_shared(&Vb[1][0]);

    const int qk_r = (lane & 7) + ((lane & 16) ? 8 : 0);
    const int qk_c = (lane & 8) ? 8 : 0;
    const uint32_t offK = (uint32_t)((qk_r * KPITCH + qk_c) * 2);
    const int v_r = (lane & 7) + ((lane & 8) ? 8 : 0);
    const int v_c = (lane & 16) ? 8 : 0;
    const uint32_t offV = (uint32_t)((v_r * KPITCH + v_c) * 2);
    const uint32_t NPOFF = 16 * KPITCH * 2;

    const float SC = 0.1803368801111244f;  // (1/sqrt(64)) * log2(e)

    // Q fragments fp16, pre-scaled by SC
    uint32_t qh[2][4][4];
#pragma unroll
    for (int rf = 0; rf < 2; ++rf)
#pragma unroll
        for (int kc = 0; kc < 4; ++kc)
#pragma unroll
            for (int p = 0; p < 4; ++p) {
                int r = row0 + rf * 16 + g + (p & 1) * 8;
                int d = kc * 16 + (p >> 1) * 8 + qq * 2;
                float2 f = *reinterpret_cast<const float2*>(Qb + (size_t)r * HD + d);
                qh[rf][kc][p] = packh2(f.x * SC, f.y * SC);
            }

    // per-row -log2(rowsum) from pass A
    float linv[2][2];
#pragma unroll
    for (int rf = 0; rf < 2; ++rf)
#pragma unroll
        for (int h = 0; h < 2; ++h)
            linv[rf][h] = LinvG[bh * SEQ + row0 + rf * 16 + g + h * 8];

    float o[2][8][4] = {};
    prefetch_tile(bK0, Kb16, tid);
    prefetch_tile(bV0, Vb16, tid);
    cp_commit();
    for (int kt = 0; kt < NT; ++kt) {
        if (kt + 1 < NT) {
            const uint32_t dK = (kt & 1) ? bK0 : bK1;
            const uint32_t dV = (kt & 1) ? bV0 : bV1;
            prefetch_tile(dK, Kb16 + (size_t)(kt + 1) * BN * HD, tid);
            prefetch_tile(dV, Vb16 + (size_t)(kt + 1) * BN * HD, tid);
            cp_commit();
            cp_wait<1>();
        } else {
            cp_wait<0>();
        }
        __syncthreads();
        const uint32_t aK = ((kt & 1) ? bK1 : bK0) + offK;
        const uint32_t aV = ((kt & 1) ? bV1 : bV0) + offV;

        // np-major: per 16-key group, QK -> exp(s+linv) -> store -> pack -> AV
#pragma unroll
        for (int np = 0; np < 4; ++np) {
            uint32_t h[4][4];
#pragma unroll
            for (int kc = 0; kc < 4; ++kc)
                ldsm_x4(h[kc][0], h[kc][1], h[kc][2], h[kc][3],
                        aK + np * NPOFF + kc * 32);
            float ca[2][4] = {}, cb[2][4] = {};
#pragma unroll
            for (int rf = 0; rf < 2; ++rf)
#pragma unroll
                for (int kc = 0; kc < 4; ++kc) {
                    mma16816(ca[rf], qh[rf][kc], h[kc][0], h[kc][1]);
                    mma16816(cb[rf], qh[rf][kc], h[kc][2], h[kc][3]);
                }

            uint32_t ah[2][4];
#pragma unroll
            for (int rf = 0; rf < 2; ++rf) {
                const float l0 = linv[rf][0], l1 = linv[rf][1];
                ca[rf][0] = ex2f(ca[rf][0] + l0);
                ca[rf][1] = ex2f(ca[rf][1] + l0);
                ca[rf][2] = ex2f(ca[rf][2] + l1);
                ca[rf][3] = ex2f(ca[rf][3] + l1);
                cb[rf][0] = ex2f(cb[rf][0] + l0);
                cb[rf][1] = ex2f(cb[rf][1] + l0);
                cb[rf][2] = ex2f(cb[rf][2] + l1);
                cb[rf][3] = ex2f(cb[rf][3] + l1);
                float* arow0 = Ab + (size_t)(row0 + rf * 16 + g) * SEQ +
                               kt * BN + 16 * np + qq * 4;
                __stcs(reinterpret_cast<float4*>(arow0),
                       make_float4(ca[rf][0], ca[rf][1], cb[rf][0], cb[rf][1]));
                __stcs(reinterpret_cast<float4*>(arow0 + 8 * SEQ),
                       make_float4(ca[rf][2], ca[rf][3], cb[rf][2], cb[rf][3]));
                ah[rf][0] = packh2(ca[rf][0], ca[rf][1]);
                ah[rf][1] = packh2(ca[rf][2], ca[rf][3]);
                ah[rf][2] = packh2(cb[rf][0], cb[rf][1]);
                ah[rf][3] = packh2(cb[rf][2], cb[rf][3]);
            }

#pragma unroll
            for (int nd = 0; nd < 4; ++nd) {
                uint32_t v0, v1, v2, v3;
                ldsm_x4_t(v0, v1, v2, v3, aV + np * NPOFF + nd * 32);
#pragma unroll
                for (int rf = 0; rf < 2; ++rf) {
                    mma16816(o[rf][2 * nd], ah[rf], v0, v1);
                    mma16816(o[rf][2 * nd + 1], ah[rf], v2, v3);
                }
            }
        }
        __syncthreads();
    }

    // ---- write O ----
#pragma unroll
    for (int rf = 0; rf < 2; ++rf)
#pragma unroll
        for (int nt = 0; nt < 8; ++nt) {
            int col = nt * 8 + qq * 2;
            int r = row0 + rf * 16 + g;
            *reinterpret_cast<float2*>(Ob + (size_t)r * HD + col) =
                make_float2(o[rf][nt][0], o[rf][nt][1]);
            *reinterpret_cast<float2*>(Ob + (size_t)(r + 8) * HD + col) =
                make_float2(o[rf][nt][2], o[rf][nt][3]);
        }
}

extern "C" void kernel_launch(void* const* d_in, const int* in_sizes, int n_in,
                              void* d_out, int out_size) {
    const float* q = (const float*)d_in[0];
    const float* k = (const float*)d_in[1];
    const float* v = (const float*)d_in[2];
    (void)in_sizes; (void)n_in; (void)out_size;
    const int n4 = BHN * SEQ * HD / 4;
    convert_kernel<<<(2 * n4) / 256, 256>>>(k, v);
    dim3 grid(SEQ / BM, BHN);
    rowsum_kernel<<<grid, NTHREADS>>>(q);
    attn_kernel<<<grid, NTHREADS>>>(q, (float*)d_out);
}

// round 12
// speedup vs baseline: 1.3859x; 1.0658x over previous
#include <cuda_runtime.h>
#include <cuda_fp16.h>
#include <cstdint>

#define BHN 16
#define SEQ 4096
#define HD 64
#define BM 128
#define BN 64
#define NTHREADS 128
#define KPITCH 72   // smem row pitch in halves (144B rows -> conflict-free LDSM)
#define NT (SEQ / BN)
#define SPLIT 2
#define HT (NT / SPLIT)   // key-tiles per split CTA

// fp16 scratch copies of K and V (converted once per launch)
__device__ __half2 Ksc[BHN * SEQ * HD / 2];
__device__ __half2 Vsc[BHN * SEQ * HD / 2];
// per-row -log2(rowsum)
__device__ float LinvG[BHN * SEQ];
// partial O per key-split
__device__ float OPart[SPLIT * BHN * SEQ * HD];

__device__ __forceinline__ float ex2f(float x) {
    float y;
    asm("ex2.approx.f32 %0, %1;" : "=f"(y) : "f"(x));
    return y;
}

__device__ __forceinline__ uint32_t h2ex2(uint32_t x) {
    uint32_t y;
    asm("ex2.approx.f16x2 %0, %1;" : "=r"(y) : "r"(x));
    return y;
}

__device__ __forceinline__ uint32_t packh2(float a, float b) {
    __half2 t = __floats2half2_rn(a, b);
    return reinterpret_cast<uint32_t&>(t);
}

__device__ __forceinline__ uint32_t hadd2u(uint32_t a, uint32_t b) {
    __half2 r = __hadd2(reinterpret_cast<__half2&>(a), reinterpret_cast<__half2&>(b));
    return reinterpret_cast<uint32_t&>(r);
}

__device__ __forceinline__ void mma16816(float c[4], const uint32_t a[4],
                                         uint32_t b0, uint32_t b1) {
    asm volatile(
        "mma.sync.aligned.m16n8k16.row.col.f32.f16.f16.f32 "
        "{%0,%1,%2,%3},{%4,%5,%6,%7},{%8,%9},{%0,%1,%2,%3};"
        : "+f"(c[0]), "+f"(c[1]), "+f"(c[2]), "+f"(c[3])
        : "r"(a[0]), "r"(a[1]), "r"(a[2]), "r"(a[3]), "r"(b0), "r"(b1));
}

__device__ __forceinline__ void mma16816h(uint32_t c[2], const uint32_t a[4],
                                          uint32_t b0, uint32_t b1) {
    asm volatile(
        "mma.sync.aligned.m16n8k16.row.col.f16.f16.f16.f16 "
        "{%0,%1},{%2,%3,%4,%5},{%6,%7},{%0,%1};"
        : "+r"(c[0]), "+r"(c[1])
        : "r"(a[0]), "r"(a[1]), "r"(a[2]), "r"(a[3]), "r"(b0), "r"(b1));
}

__device__ __forceinline__ void ldsm_x4(uint32_t& r0, uint32_t& r1, uint32_t& r2,
                                        uint32_t& r3, uint32_t addr) {
    asm volatile("ldmatrix.sync.aligned.m8n8.x4.shared.b16 {%0,%1,%2,%3},[%4];"
                 : "=r"(r0), "=r"(r1), "=r"(r2), "=r"(r3) : "r"(addr));
}

__device__ __forceinline__ void ldsm_x4_t(uint32_t& r0, uint32_t& r1, uint32_t& r2,
                                          uint32_t& r3, uint32_t addr) {
    asm volatile("ldmatrix.sync.aligned.m8n8.x4.trans.shared.b16 {%0,%1,%2,%3},[%4];"
                 : "=r"(r0), "=r"(r1), "=r"(r2), "=r"(r3) : "r"(addr));
}

__device__ __forceinline__ void cpasync16(uint32_t dst, const void* src) {
    asm volatile("cp.async.cg.shared.global [%0],[%1],16;" :: "r"(dst), "l"(src));
}
__device__ __forceinline__ void cp_commit() {
    asm volatile("cp.async.commit_group;");
}
template <int N>
__device__ __forceinline__ void cp_wait() {
    asm volatile("cp.async.wait_group %0;" :: "n"(N));
}

// prefetch one [BN x HD] fp16 tile, rows permuted within each 16-key group.
__device__ __forceinline__ void prefetch_tile(uint32_t dstbase, const __half* src,
                                              int tid) {
#pragma unroll
    for (int t = 0; t < 4; ++t) {
        int i = tid + t * NTHREADS;
        int r = i >> 3;
        int c8 = (i & 7) << 3;
        int s = r & 15;
        int a = ((s & 6) << 1) | ((s & 8) >> 2) | (s & 1);
        int srcr = (r & 48) | a;
        cpasync16(dstbase + (uint32_t)((r * KPITCH + c8) * 2), src + srcr * HD + c8);
    }
}

// ---------------- pre-conversion kernel ----------------
__global__ void __launch_bounds__(256)
convert_kernel(const float* __restrict__ K, const float* __restrict__ V) {
    const int n4 = BHN * SEQ * HD / 4;
    int i = blockIdx.x * blockDim.x + threadIdx.x;
    if (i < n4) {
        float4 f = reinterpret_cast<const float4*>(K)[i];
        Ksc[2 * i] = __floats2half2_rn(f.x, f.y);
        Ksc[2 * i + 1] = __floats2half2_rn(f.z, f.w);
    } else {
        int j = i - n4;
        float4 f = reinterpret_cast<const float4*>(V)[j];
        Vsc[2 * j] = __floats2half2_rn(f.x, f.y);
        Vsc[2 * j + 1] = __floats2half2_rn(f.z, f.w);
    }
}

// ---------------- PASS A kernel: row sums via f16-accum MMA ----------------
__global__ void __launch_bounds__(NTHREADS, 5)
rowsum_kernel(const float* __restrict__ Qg) {
    __shared__ __half Kb[2][BN * KPITCH];

    const int bh = blockIdx.y;
    const float* Qb = Qg + (size_t)bh * SEQ * HD;
    const __half* Kb16 = reinterpret_cast<const __half*>(Ksc) + (size_t)bh * SEQ * HD;

    const int tid = threadIdx.x;
    const int warp = tid >> 5;
    const int lane = tid & 31;
    const int g = lane >> 2;
    const int qq = lane & 3;
    const int row0 = blockIdx.x * BM + warp * 32;

    const uint32_t bK0 = (uint32_t)__cvta_generic_to_shared(&Kb[0][0]);
    const uint32_t bK1 = (uint32_t)__cvta_generic_to_shared(&Kb[1][0]);

    const int qk_r = (lane & 7) + ((lane & 16) ? 8 : 0);
    const int qk_c = (lane & 8) ? 8 : 0;
    const uint32_t offK = (uint32_t)((qk_r * KPITCH + qk_c) * 2);
    const uint32_t NPOFF = 16 * KPITCH * 2;

    const float SC = 0.1803368801111244f;

    uint32_t qh[2][4][4];
#pragma unroll
    for (int rf = 0; rf < 2; ++rf)
#pragma unroll
        for (int kc = 0; kc < 4; ++kc)
#pragma unroll
            for (int p = 0; p < 4; ++p) {
                int r = row0 + rf * 16 + g + (p & 1) * 8;
                int d = kc * 16 + (p >> 1) * 8 + qq * 2;
                float2 f = *reinterpret_cast<const float2*>(Qb + (size_t)r * HD + d);
                qh[rf][kc][p] = packh2(f.x * SC, f.y * SC);
            }

    float rs[2][2] = {};
    prefetch_tile(bK0, Kb16, tid);
    cp_commit();
    for (int kt = 0; kt < NT; ++kt) {
        if (kt + 1 < NT) {
            prefetch_tile((kt & 1) ? bK0 : bK1, Kb16 + (size_t)(kt + 1) * BN * HD, tid);
            cp_commit();
            cp_wait<1>();
        } else {
            cp_wait<0>();
        }
        __syncthreads();
        const uint32_t aK = ((kt & 1) ? bK1 : bK0) + offK;
        uint32_t acc[2][2] = {{0, 0}, {0, 0}};
#pragma unroll
        for (int np = 0; np < 4; ++np) {
            uint32_t h[4][4];
#pragma unroll
            for (int kc = 0; kc < 4; ++kc)
                ldsm_x4(h[kc][0], h[kc][1], h[kc][2], h[kc][3],
                        aK + np * NPOFF + kc * 32);
#pragma unroll
            for (int rf = 0; rf < 2; ++rf) {
                uint32_t ca[2] = {0, 0}, cb[2] = {0, 0};
#pragma unroll
                for (int kc = 0; kc < 4; ++kc) {
                    mma16816h(ca, qh[rf][kc], h[kc][0], h[kc][1]);
                    mma16816h(cb, qh[rf][kc], h[kc][2], h[kc][3]);
                }
                acc[rf][0] = hadd2u(acc[rf][0], hadd2u(h2ex2(ca[0]), h2ex2(cb[0])));
                acc[rf][1] = hadd2u(acc[rf][1], hadd2u(h2ex2(ca[1]), h2ex2(cb[1])));
            }
        }
#pragma unroll
        for (int rf = 0; rf < 2; ++rf) {
            float2 f0 = __half22float2(reinterpret_cast<__half2&>(acc[rf][0]));
            float2 f1 = __half22float2(reinterpret_cast<__half2&>(acc[rf][1]));
            rs[rf][0] += f0.x + f0.y;
            rs[rf][1] += f1.x + f1.y;
        }
        __syncthreads();
    }
#pragma unroll
    for (int rf = 0; rf < 2; ++rf)
#pragma unroll
        for (int h = 0; h < 2; ++h) {
            float v = rs[rf][h];
            v += __shfl_xor_sync(0xffffffffu, v, 1);
            v += __shfl_xor_sync(0xffffffffu, v, 2);
            if (qq == 0)
                LinvG[bh * SEQ + row0 + rf * 16 + g + h * 8] = -__log2f(v);
        }
}

// ---------------- PASS B kernel: key-split halves ----------
__global__ void __launch_bounds__(NTHREADS, 3)
attn_kernel(const float* __restrict__ Qg, float* __restrict__ out) {
    __shared__ __half Kb[2][BN * KPITCH];
    __shared__ __half Vb[2][BN * KPITCH];

    const int bh = blockIdx.y;
    const int kz = blockIdx.z;          // key-split index
    const int kt0 = kz * HT;
    const float* Qb = Qg + (size_t)bh * SEQ * HD;
    const __half* Kb16 = reinterpret_cast<const __half*>(Ksc) + (size_t)bh * SEQ * HD +
                         (size_t)kt0 * BN * HD;
    const __half* Vb16 = reinterpret_cast<const __half*>(Vsc) + (size_t)bh * SEQ * HD +
                         (size_t)kt0 * BN * HD;
    float* OPb = OPart + ((size_t)kz * BHN + bh) * SEQ * HD;
    float* Ab = out + (size_t)BHN * SEQ * HD + (size_t)bh * SEQ * SEQ;

    const int tid = threadIdx.x;
    const int warp = tid >> 5;
    const int lane = tid & 31;
    const int g = lane >> 2;
    const int qq = lane & 3;
    const int row0 = blockIdx.x * BM + warp * 32;

    const uint32_t bK0 = (uint32_t)__cvta_generic_to_shared(&Kb[0][0]);
    const uint32_t bK1 = (uint32_t)__cvta_generic_to_shared(&Kb[1][0]);
    const uint32_t bV0 = (uint32_t)__cvta_generic_to_shared(&Vb[0][0]);
    const uint32_t bV1 = (uint32_t)__cvta_generic_to_shared(&Vb[1][0]);

    const int qk_r = (lane & 7) + ((lane & 16) ? 8 : 0);
    const int qk_c = (lane & 8) ? 8 : 0;
    const uint32_t offK = (uint32_t)((qk_r * KPITCH + qk_c) * 2);
    const int v_r = (lane & 7) + ((lane & 8) ? 8 : 0);
    const int v_c = (lane & 16) ? 8 : 0;
    const uint32_t offV = (uint32_t)((v_r * KPITCH + v_c) * 2);
    const uint32_t NPOFF = 16 * KPITCH * 2;

    const float SC = 0.1803368801111244f;

    uint32_t qh[2][4][4];
#pragma unroll
    for (int rf = 0; rf < 2; ++rf)
#pragma unroll
        for (int kc = 0; kc < 4; ++kc)
#pragma unroll
            for (int p = 0; p < 4; ++p) {
                int r = row0 + rf * 16 + g + (p & 1) * 8;
                int d = kc * 16 + (p >> 1) * 8 + qq * 2;
                float2 f = *reinterpret_cast<const float2*>(Qb + (size_t)r * HD + d);
                qh[rf][kc][p] = packh2(f.x * SC, f.y * SC);
            }

    float linv[2][2];
#pragma unroll
    for (int rf = 0; rf < 2; ++rf)
#pragma unroll
        for (int h = 0; h < 2; ++h)
            linv[rf][h] = LinvG[bh * SEQ + row0 + rf * 16 + g + h * 8];

    float o[2][8][4] = {};
    prefetch_tile(bK0, Kb16, tid);
    prefetch_tile(bV0, Vb16, tid);
    cp_commit();
    for (int kt = 0; kt < HT; ++kt) {
        if (kt + 1 < HT) {
            const uint32_t dK = (kt & 1) ? bK0 : bK1;
            const uint32_t dV = (kt & 1) ? bV0 : bV1;
            prefetch_tile(dK, Kb16 + (size_t)(kt + 1) * BN * HD, tid);
            prefetch_tile(dV, Vb16 + (size_t)(kt + 1) * BN * HD, tid);
            cp_commit();
            cp_wait<1>();
        } else {
            cp_wait<0>();
        }
        __syncthreads();
        const uint32_t aK = ((kt & 1) ? bK1 : bK0) + offK;
        const uint32_t aV = ((kt & 1) ? bV1 : bV0) + offV;

#pragma unroll
        for (int np = 0; np < 4; ++np) {
            uint32_t h[4][4];
#pragma unroll
            for (int kc = 0; kc < 4; ++kc)
                ldsm_x4(h[kc][0], h[kc][1], h[kc][2], h[kc][3],
                        aK + np * NPOFF + kc * 32);
            float ca[2][4] = {}, cb[2][4] = {};
#pragma unroll
            for (int rf = 0; rf < 2; ++rf)
#pragma unroll
                for (int kc = 0; kc < 4; ++kc) {
                    mma16816(ca[rf], qh[rf][kc], h[kc][0], h[kc][1]);
                    mma16816(cb[rf], qh[rf][kc], h[kc][2], h[kc][3]);
                }

            uint32_t ah[2][4];
#pragma unroll
            for (int rf = 0; rf < 2; ++rf) {
                const float l0 = linv[rf][0], l1 = linv[rf][1];
                ca[rf][0] = ex2f(ca[rf][0] + l0);
                ca[rf][1] = ex2f(ca[rf][1] + l0);
                ca[rf][2] = ex2f(ca[rf][2] + l1);
                ca[rf][3] = ex2f(ca[rf][3] + l1);
                cb[rf][0] = ex2f(cb[rf][0] + l0);
                cb[rf][1] = ex2f(cb[rf][1] + l0);
                cb[rf][2] = ex2f(cb[rf][2] + l1);
                cb[rf][3] = ex2f(cb[rf][3] + l1);
                float* arow0 = Ab + (size_t)(row0 + rf * 16 + g) * SEQ +
                               (kt0 + kt) * BN + 16 * np + qq * 4;
                __stcs(reinterpret_cast<float4*>(arow0),
                       make_float4(ca[rf][0], ca[rf][1], cb[rf][0], cb[rf][1]));
                __stcs(reinterpret_cast<float4*>(arow0 + 8 * SEQ),
                       make_float4(ca[rf][2], ca[rf][3], cb[rf][2], cb[rf][3]));
                ah[rf][0] = packh2(ca[rf][0], ca[rf][1]);
                ah[rf][1] = packh2(ca[rf][2], ca[rf][3]);
                ah[rf][2] = packh2(cb[rf][0], cb[rf][1]);
                ah[rf][3] = packh2(cb[rf][2], cb[rf][3]);
            }

#pragma unroll
            for (int nd = 0; nd < 4; ++nd) {
                uint32_t v0, v1, v2, v3;
                ldsm_x4_t(v0, v1, v2, v3, aV + np * NPOFF + nd * 32);
#pragma unroll
                for (int rf = 0; rf < 2; ++rf) {
                    mma16816(o[rf][2 * nd], ah[rf], v0, v1);
                    mma16816(o[rf][2 * nd + 1], ah[rf], v2, v3);
                }
            }
        }
        __syncthreads();
    }

    // ---- write partial O ----
#pragma unroll
    for (int rf = 0; rf < 2; ++rf)
#pragma unroll
        for (int nt = 0; nt < 8; ++nt) {
            int col = nt * 8 + qq * 2;
            int r = row0 + rf * 16 + g;
            *reinterpret_cast<float2*>(OPb + (size_t)r * HD + col) =
                make_float2(o[rf][nt][0], o[rf][nt][1]);
            *reinterpret_cast<float2*>(OPb + (size_t)(r + 8) * HD + col) =
                make_float2(o[rf][nt][2], o[rf][nt][3]);
        }
}

// ---------------- O reduce: O = OPart[0] + OPart[1] ----------------
__global__ void __launch_bounds__(256)
reduce_kernel(float* __restrict__ out) {
    const int n4 = BHN * SEQ * HD / 4;
    int i = blockIdx.x * blockDim.x + threadIdx.x;
    if (i < n4) {
        const float4* a = reinterpret_cast<const float4*>(OPart);
        float4 x = a[i];
        float4 y = a[i + n4];
        reinterpret_cast<float4*>(out)[i] =
            make_float4(x.x + y.x, x.y + y.y, x.z + y.z, x.w + y.w);
    }
}

extern "C" void kernel_launch(void* const* d_in, const int* in_sizes, int n_in,
                              void* d_out, int out_size) {
    const float* q = (const float*)d_in[0];
    const float* k = (const float*)d_in[1];
    const float* v = (const float*)d_in[2];
    (void)in_sizes; (void)n_in; (void)out_size;
    const int n4 = BHN * SEQ * HD / 4;
    convert_kernel<<<(2 * n4) / 256, 256>>>(k, v);
    dim3 grid(SEQ / BM, BHN);
    rowsum_kernel<<<grid, NTHREADS>>>(q);
    dim3 gridB(SEQ / BM, BHN, SPLIT);
    attn_kernel<<<gridB, NTHREADS>>>(q, (float*)d_out);
    reduce_kernel<<<(n4 + 255) / 256, 256>>>((float*)d_out);
}